// round 16
// baseline (speedup 1.0000x reference)
#include <cuda_runtime.h>
#include <cuda_bf16.h>
#include <math.h>

#define BB 32
#define NN 4096
#define KVN 1024
#define DD 1024
#define HH 16
#define LL 2
#define MAXFV 4096
#define MS 32   // mean slices

// ---------- scratch ----------
__device__ __align__(16) float g_q[64 * DD];
__device__ __align__(16) float g_x[64 * DD];
__device__ __align__(16) float g_qkv[64 * 3 * DD];
__device__ __align__(16) float g_attn[64 * DD];
__device__ __align__(16) float g_qp[BB * DD];
__device__ __align__(16) float g_u[BB * HH * DD];
__device__ __align__(16) float g_c[BB * HH * DD];
__device__ __align__(16) float g_scores[BB * HH * NN];
__device__ __align__(16) float g_part[16 * 64 * 4096];
__device__ __align__(16) float g_cpart[16 * BB * HH * DD];
__device__ __align__(16) float g_mpart[MS * BB * DD];
__device__ __align__(16) float g_h[64 * 4096];
// bf16 staged copies of the streamed tensors
__device__ __align__(16) __nv_bfloat16 g_ftb[(size_t)BB * NN * DD];
__device__ __align__(16) __nv_bfloat16 g_kvb[(size_t)BB * KVN * DD];

// ---------- packed f32x2 / bf16 helpers ----------
__device__ __forceinline__ unsigned long long pack2(float lo, float hi) {
    unsigned long long r;
    asm("mov.b64 %0, {%1, %2};" : "=l"(r) : "f"(lo), "f"(hi));
    return r;
}
__device__ __forceinline__ float2 unpack2(unsigned long long v) {
    float2 r;
    asm("mov.b64 {%0, %1}, %2;" : "=f"(r.x), "=f"(r.y) : "l"(v));
    return r;
}
__device__ __forceinline__ void ffma2(unsigned long long& d, unsigned long long a,
                                      unsigned long long b) {
    asm("fma.rn.f32x2 %0, %1, %2, %0;" : "+l"(d) : "l"(a), "l"(b));
}
__device__ __forceinline__ unsigned packbf(float a, float b) {
    __nv_bfloat162 t = __floats2bfloat162_rn(a, b);
    return *reinterpret_cast<unsigned*>(&t);
}
// packed bf16x2 -> packed f32x2 {lo,hi}
__device__ __forceinline__ unsigned long long bfpair(unsigned v) {
    unsigned lo = v << 16, hi = v & 0xffff0000u;
    unsigned long long r;
    asm("mov.b64 %0, {%1, %2};" : "=l"(r) : "r"(lo), "r"(hi));
    return r;
}

// ---------- block reductions ----------
__device__ __forceinline__ float blkredSum(float v) {
    __shared__ float sm[8];
    __shared__ float outv;
    int tid = threadIdx.x;
#pragma unroll
    for (int o = 16; o; o >>= 1) v += __shfl_xor_sync(0xffffffffu, v, o);
    if ((tid & 31) == 0) sm[tid >> 5] = v;
    __syncthreads();
    if (tid == 0) {
        float a = 0.f;
        int nw = blockDim.x >> 5;
        for (int w = 0; w < nw; w++) a += sm[w];
        outv = a;
    }
    __syncthreads();
    float r = outv;
    __syncthreads();
    return r;
}

__device__ __forceinline__ float blkredMax(float v) {
    __shared__ float sm[8];
    __shared__ float outv;
    int tid = threadIdx.x;
#pragma unroll
    for (int o = 16; o; o >>= 1) v = fmaxf(v, __shfl_xor_sync(0xffffffffu, v, o));
    if ((tid & 31) == 0) sm[tid >> 5] = v;
    __syncthreads();
    if (tid == 0) {
        float a = -1e30f;
        int nw = blockDim.x >> 5;
        for (int w = 0; w < nw; w++) a = fmaxf(a, sm[w]);
        outv = a;
    }
    __syncthreads();
    float r = outv;
    __syncthreads();
    return r;
}

// ---------- partial mean of frame_tokens + bf16 conversion: grid (2, BB, MS), block 128 ----------
__global__ void meanpart_k(const float* __restrict__ X) {
    int b = blockIdx.y, s = blockIdx.z;
    int c0 = blockIdx.x * 512 + threadIdx.x * 4;
    const int RS = NN / MS;
    const float* base = X + ((size_t)b * NN + (size_t)s * RS) * DD + c0;
    __nv_bfloat16* ob = g_ftb + ((size_t)b * NN + (size_t)s * RS) * DD + c0;
    float4 acc = make_float4(0.f, 0.f, 0.f, 0.f);
    for (int j = 0; j < RS; j += 4) {
        float4 v0 = *(const float4*)(base + (size_t)(j + 0) * DD);
        float4 v1 = *(const float4*)(base + (size_t)(j + 1) * DD);
        float4 v2 = *(const float4*)(base + (size_t)(j + 2) * DD);
        float4 v3 = *(const float4*)(base + (size_t)(j + 3) * DD);
        uint2 o0 = make_uint2(packbf(v0.x, v0.y), packbf(v0.z, v0.w));
        uint2 o1 = make_uint2(packbf(v1.x, v1.y), packbf(v1.z, v1.w));
        uint2 o2 = make_uint2(packbf(v2.x, v2.y), packbf(v2.z, v2.w));
        uint2 o3 = make_uint2(packbf(v3.x, v3.y), packbf(v3.z, v3.w));
        *(uint2*)(ob + (size_t)(j + 0) * DD) = o0;
        *(uint2*)(ob + (size_t)(j + 1) * DD) = o1;
        *(uint2*)(ob + (size_t)(j + 2) * DD) = o2;
        *(uint2*)(ob + (size_t)(j + 3) * DD) = o3;
        acc.x += (v0.x + v1.x) + (v2.x + v3.x);
        acc.y += (v0.y + v1.y) + (v2.y + v3.y);
        acc.z += (v0.z + v1.z) + (v2.z + v3.z);
        acc.w += (v0.w + v1.w) + (v2.w + v3.w);
    }
    *(float4*)(g_mpart + (size_t)(s * BB + b) * DD + c0) = acc;
}

// ---------- fp32 -> bf16 convert (kv_salient): grid total/1024, block 256 ----------
__global__ void conv_k(const float* __restrict__ src, __nv_bfloat16* __restrict__ dst) {
    size_t i = ((size_t)blockIdx.x * 256 + threadIdx.x) * 4;
    float4 v = *(const float4*)(src + i);
    uint2 o = make_uint2(packbf(v.x, v.y), packbf(v.z, v.w));
    *(uint2*)(dst + i) = o;
}

// ---------- q init: grid 256, block 256 ----------
__global__ void initq_k(const float* __restrict__ max_init,
                        const float* __restrict__ qbase,
                        const float* __restrict__ rolew,
                        const float* __restrict__ timew,
                        const int* __restrict__ fidx) {
    int idx = blockIdx.x * 256 + threadIdx.x;
    int b = idx >> 11, r = idx & 2047, t = r >> 10, d = r & 1023;
    float base;
    if (t == 0) {
        float m = 0.f;
#pragma unroll
        for (int s = 0; s < MS; s++) m += g_mpart[(size_t)(s * BB + b) * DD + d];
        base = m * (1.0f / NN);
    } else {
        base = max_init[b * DD + d];
    }
    int fi = fidx[b];
    fi = fi < 0 ? 0 : (fi > MAXFV - 1 ? MAXFV - 1 : fi);
    g_q[idx] = base + qbase[t * DD + d] + rolew[t * DD + d] + timew[(size_t)fi * DD + d];
}

// ---------- LayerNorm rows: grid rows, block 256 ----------
__global__ void ln_k(const float* __restrict__ in, const float* __restrict__ gg,
                     const float* __restrict__ bb, float* __restrict__ out) {
    int row = blockIdx.x, tid = threadIdx.x;
    float4 xv = ((const float4*)(in + (size_t)row * DD))[tid];
    float s = blkredSum(xv.x + xv.y + xv.z + xv.w);
    float mean = s * (1.0f / DD);
    float d0 = xv.x - mean, d1 = xv.y - mean, d2 = xv.z - mean, d3 = xv.w - mean;
    float ss = blkredSum(d0 * d0 + d1 * d1 + d2 * d2 + d3 * d3);
    float inv = rsqrtf(ss * (1.0f / DD) + 1e-5f);
    float4 g4 = ((const float4*)gg)[tid];
    float4 b4 = ((const float4*)bb)[tid];
    float4 o;
    o.x = d0 * inv * g4.x + b4.x;
    o.y = d1 * inv * g4.y + b4.y;
    o.z = d2 * inv * g4.z + b4.z;
    o.w = d3 * inv * g4.w + b4.w;
    ((float4*)(out + (size_t)row * DD))[tid] = o;
}

// ---------- split-K GEMM, double-buffered smem + register prefetch + FFMA2 ----------
// part[bt][s][m][n] = sum_{k in slice} A[m,k]*W[n,k]
// grid (Ntot/64, 1, nbatch*SK), block 256
__global__ void gemm_k(const float* __restrict__ A, int lda, long long sA,
                       const float* __restrict__ W, int ldw, long long sW,
                       float* __restrict__ part, int Ntot, int M, int Ktot, int SK) {
    int z = blockIdx.z;
    int bt = z / SK, s = z - bt * SK;
    A += (long long)bt * sA;
    W += (long long)bt * sW;
    float* P = part + ((long long)(bt * SK + s) * M) * Ntot;
    int Ks = Ktot / SK, kbase = s * Ks;
    int n0 = blockIdx.x * 64;
    __shared__ __align__(16) float As[2][16][68];
    __shared__ __align__(16) float Ws[2][16][68];
    int tid = threadIdx.x;
    int tx = tid & 15, ty = tid >> 4;
    int lr = tid >> 2, lc = (tid & 3) * 4;
    unsigned long long acc01[4], acc23[4];
#pragma unroll
    for (int j = 0; j < 4; j++) { acc01[j] = 0ull; acc23[j] = 0ull; }
    const float* Ap = A + (long long)lr * lda + kbase + lc;
    const float* Wp = W + (long long)(n0 + lr) * ldw + kbase + lc;
    int nc = Ks >> 4;
    float4 av = make_float4(0.f, 0.f, 0.f, 0.f), wv;
    if (lr < M) av = *(const float4*)Ap;
    wv = *(const float4*)Wp;
    As[0][lc + 0][lr] = av.x; As[0][lc + 1][lr] = av.y;
    As[0][lc + 2][lr] = av.z; As[0][lc + 3][lr] = av.w;
    Ws[0][lc + 0][lr] = wv.x; Ws[0][lc + 1][lr] = wv.y;
    Ws[0][lc + 2][lr] = wv.z; Ws[0][lc + 3][lr] = wv.w;
    __syncthreads();
    for (int c = 0; c < nc; c++) {
        int cur = c & 1;
        if (c + 1 < nc) {
            av = make_float4(0.f, 0.f, 0.f, 0.f);
            if (lr < M) av = *(const float4*)(Ap + (c + 1) * 16);
            wv = *(const float4*)(Wp + (c + 1) * 16);
        }
#pragma unroll
        for (int kk = 0; kk < 16; kk++) {
            float4 a4 = *(const float4*)&As[cur][kk][ty * 4];
            float4 w4 = *(const float4*)&Ws[cur][kk][tx * 4];
            unsigned long long a01 = pack2(a4.x, a4.y);
            unsigned long long a23 = pack2(a4.z, a4.w);
            unsigned long long w0 = pack2(w4.x, w4.x);
            unsigned long long w1 = pack2(w4.y, w4.y);
            unsigned long long w2 = pack2(w4.z, w4.z);
            unsigned long long w3 = pack2(w4.w, w4.w);
            ffma2(acc01[0], a01, w0); ffma2(acc23[0], a23, w0);
            ffma2(acc01[1], a01, w1); ffma2(acc23[1], a23, w1);
            ffma2(acc01[2], a01, w2); ffma2(acc23[2], a23, w2);
            ffma2(acc01[3], a01, w3); ffma2(acc23[3], a23, w3);
        }
        if (c + 1 < nc) {
            int nxt = cur ^ 1;
            As[nxt][lc + 0][lr] = av.x; As[nxt][lc + 1][lr] = av.y;
            As[nxt][lc + 2][lr] = av.z; As[nxt][lc + 3][lr] = av.w;
            Ws[nxt][lc + 0][lr] = wv.x; Ws[nxt][lc + 1][lr] = wv.y;
            Ws[nxt][lc + 2][lr] = wv.z; Ws[nxt][lc + 3][lr] = wv.w;
        }
        __syncthreads();
    }
    float2 r0 = unpack2(acc01[0]), r1 = unpack2(acc01[1]);
    float2 r2 = unpack2(acc01[2]), r3 = unpack2(acc01[3]);
    float2 s0 = unpack2(acc23[0]), s1 = unpack2(acc23[1]);
    float2 s2 = unpack2(acc23[2]), s3 = unpack2(acc23[3]);
    int m0 = ty * 4, nn = n0 + tx * 4;
    if (m0 + 0 < M) *(float4*)&P[(long long)(m0 + 0) * Ntot + nn] = make_float4(r0.x, r1.x, r2.x, r3.x);
    if (m0 + 1 < M) *(float4*)&P[(long long)(m0 + 1) * Ntot + nn] = make_float4(r0.y, r1.y, r2.y, r3.y);
    if (m0 + 2 < M) *(float4*)&P[(long long)(m0 + 2) * Ntot + nn] = make_float4(s0.x, s1.x, s2.x, s3.x);
    if (m0 + 3 < M) *(float4*)&P[(long long)(m0 + 3) * Ntot + nn] = make_float4(s0.y, s1.y, s2.y, s3.y);
}

// ---------- combine split-K + bias; mode 0 store, 1 gelu-store, 2 residual-add ----------
__global__ void combine_k(const float* __restrict__ part, int S, int M, int N,
                          const float* __restrict__ bias, int biasBatch,
                          float* __restrict__ dst, int dstRow, int dstBatch,
                          int mode, int total) {
    int idx = blockIdx.x * 256 + threadIdx.x;
    if (idx >= total) return;
    int bt = idx / (M * N);
    int r = idx - bt * M * N;
    int m = r / N, n = r - m * N;
    float v = 0.f;
    const float* p = part + ((long long)bt * S * M + m) * N + n;
    for (int s = 0; s < S; s++) v += p[(long long)s * M * N];
    if (bias) v += bias[bt * biasBatch + n];
    if (mode == 1) v = 0.5f * v * (1.0f + erff(v * 0.70710678118654752f));
    float* dp = dst + (long long)bt * dstBatch + (long long)m * dstRow + n;
    if (mode == 2) *dp += v; else *dp = v;
}

// ---------- self-attn over 2 tokens: grid (BB, HH), block 64 ----------
__global__ void sattn_k() {
    int b = blockIdx.x, h = blockIdx.y, i = threadIdx.x;
    int r0 = (b * 2) * 3 * DD, r1 = r0 + 3 * DD;
    int cq = h * 64 + i, ck = DD + cq, cv = 2 * DD + cq;
    float q0 = g_qkv[r0 + cq], q1 = g_qkv[r1 + cq];
    float k0 = g_qkv[r0 + ck], k1 = g_qkv[r1 + ck];
    float v0 = g_qkv[r0 + cv], v1 = g_qkv[r1 + cv];
    __shared__ float red[4][64];
    red[0][i] = q0 * k0; red[1][i] = q0 * k1;
    red[2][i] = q1 * k0; red[3][i] = q1 * k1;
    __syncthreads();
    __shared__ float ss[4];
    if (i < 4) {
        float a = 0.f;
        for (int j = 0; j < 64; j++) a += red[i][j];
        ss[i] = a * 0.125f;
    }
    __syncthreads();
    float m0 = fmaxf(ss[0], ss[1]);
    float e00 = __expf(ss[0] - m0), e01 = __expf(ss[1] - m0);
    float o0 = (e00 * v0 + e01 * v1) / (e00 + e01);
    float m1 = fmaxf(ss[2], ss[3]);
    float e10 = __expf(ss[2] - m1), e11 = __expf(ss[3] - m1);
    float o1 = (e10 * v0 + e11 * v1) / (e10 + e11);
    g_attn[(size_t)(b * 2) * DD + h * 64 + i] = o0;
    g_attn[(size_t)(b * 2 + 1) * DD + h * 64 + i] = o1;
}

// ---------- u = 0.125 * Wk_h^T (qp_h + bq_h): grid (HH, DD/64), block 256 ----------
__global__ void u_k(const float* __restrict__ Wk, const float* __restrict__ bq) {
    int h = blockIdx.x;
    int d0 = blockIdx.y * 64;
    int tid = threadIdx.x;
    __shared__ float qps[32 * 64];
    for (int t = tid; t < 2048; t += 256) {
        int b = t >> 6, i = t & 63;
        qps[t] = g_qp[b * DD + h * 64 + i] + bq[h * 64 + i];
    }
    __syncthreads();
    int d = d0 + (tid & 63);
    int bg = tid >> 6;
    float acc[8];
#pragma unroll
    for (int r = 0; r < 8; r++) acc[r] = 0.f;
    const float* wp = Wk + (size_t)(h * 64) * DD + d;
    for (int i = 0; i < 64; i++) {
        float w = wp[(size_t)i * DD];
#pragma unroll
        for (int r = 0; r < 8; r++) acc[r] += qps[(bg * 8 + r) * 64 + i] * w;
    }
#pragma unroll
    for (int r = 0; r < 8; r++)
        g_u[((size_t)(bg * 8 + r) * HH + h) * DD + d] = acc[r] * 0.125f;
}

// ---------- scores S[b,h,j] = u[b,h,:].x[b,j,:] — bf16 X, pre-dup u pairs, double-buffered ----------
// grid (Nkv/128, BB), block 128
__global__ void score_k(const __nv_bfloat16* __restrict__ X, int Nkv) {
    int b = blockIdx.y;
    int jb = blockIdx.x * 128;
    int tid = threadIdx.x;
    int tx = tid & 3, ty = tid >> 2;  // tx: h-group, ty: j-group
    __shared__ __align__(16) float Xs[2][32][132];                // [buf][kk][j]
    __shared__ __align__(16) unsigned long long Us[2][32][20];    // [buf][kk][h] = {u,u}
    unsigned long long acc01[4], acc23[4];
#pragma unroll
    for (int j = 0; j < 4; j++) { acc01[j] = 0ull; acc23[j] = 0ull; }
    const float* Ub = g_u + (size_t)b * HH * DD;
    int lr8 = tid >> 3, lc = (tid & 7) * 4;
    const __nv_bfloat16* Xp = X + ((size_t)b * Nkv + jb + lr8) * DD + lc;
    const float* Up = Ub + (size_t)lr8 * DD + lc;
    uint2 xv[8];
    float4 uv;
    // prologue: chunk 0 -> buf 0
#pragma unroll
    for (int q = 0; q < 8; q++) xv[q] = *(const uint2*)(Xp + (size_t)(q * 16) * DD);
    uv = *(const float4*)Up;
#pragma unroll
    for (int q = 0; q < 8; q++) {
        int row = lr8 + q * 16;
        Xs[0][lc + 0][row] = __uint_as_float(xv[q].x << 16);
        Xs[0][lc + 1][row] = __uint_as_float(xv[q].x & 0xffff0000u);
        Xs[0][lc + 2][row] = __uint_as_float(xv[q].y << 16);
        Xs[0][lc + 3][row] = __uint_as_float(xv[q].y & 0xffff0000u);
    }
    Us[0][lc + 0][lr8] = pack2(uv.x, uv.x);
    Us[0][lc + 1][lr8] = pack2(uv.y, uv.y);
    Us[0][lc + 2][lr8] = pack2(uv.z, uv.z);
    Us[0][lc + 3][lr8] = pack2(uv.w, uv.w);
    __syncthreads();
    const int NC = DD / 32;
    for (int c = 0; c < NC; c++) {
        int cur = c & 1;
        if (c + 1 < NC) {
            int k0 = (c + 1) * 32;
#pragma unroll
            for (int q = 0; q < 8; q++) xv[q] = *(const uint2*)(Xp + (size_t)(q * 16) * DD + k0);
            uv = *(const float4*)(Up + k0);
        }
#pragma unroll
        for (int kk = 0; kk < 32; kk++) {
            float4 a4 = *(const float4*)&Xs[cur][kk][ty * 4];
            ulonglong2 w01 = *(const ulonglong2*)&Us[cur][kk][tx * 4];
            ulonglong2 w23 = *(const ulonglong2*)&Us[cur][kk][tx * 4 + 2];
            unsigned long long a01 = pack2(a4.x, a4.y);
            unsigned long long a23 = pack2(a4.z, a4.w);
            ffma2(acc01[0], a01, w01.x); ffma2(acc23[0], a23, w01.x);
            ffma2(acc01[1], a01, w01.y); ffma2(acc23[1], a23, w01.y);
            ffma2(acc01[2], a01, w23.x); ffma2(acc23[2], a23, w23.x);
            ffma2(acc01[3], a01, w23.y); ffma2(acc23[3], a23, w23.y);
        }
        if (c + 1 < NC) {
            int nxt = cur ^ 1;
#pragma unroll
            for (int q = 0; q < 8; q++) {
                int row = lr8 + q * 16;
                Xs[nxt][lc + 0][row] = __uint_as_float(xv[q].x << 16);
                Xs[nxt][lc + 1][row] = __uint_as_float(xv[q].x & 0xffff0000u);
                Xs[nxt][lc + 2][row] = __uint_as_float(xv[q].y << 16);
                Xs[nxt][lc + 3][row] = __uint_as_float(xv[q].y & 0xffff0000u);
            }
            Us[nxt][lc + 0][lr8] = pack2(uv.x, uv.x);
            Us[nxt][lc + 1][lr8] = pack2(uv.y, uv.y);
            Us[nxt][lc + 2][lr8] = pack2(uv.z, uv.z);
            Us[nxt][lc + 3][lr8] = pack2(uv.w, uv.w);
        }
        __syncthreads();
    }
#pragma unroll
    for (int j = 0; j < 4; j++) {
        float2 p01 = unpack2(acc01[j]);
        float2 p23 = unpack2(acc23[j]);
        float* Sp = g_scores + ((size_t)b * HH + tx * 4 + j) * Nkv + jb + ty * 4;
        *(float4*)Sp = make_float4(p01.x, p01.y, p23.x, p23.y);
    }
}

// ---------- softmax in place: grid BB*HH, block 256 ----------
__global__ void softmax_k(int Nkv) {
    int tid = threadIdx.x;
    float* S = g_scores + (size_t)blockIdx.x * Nkv;
    int cnt = Nkv >> 8;
    float v[16];
    float mx = -1e30f;
    for (int c = 0; c < cnt; c++) { v[c] = S[c * 256 + tid]; mx = fmaxf(mx, v[c]); }
    mx = blkredMax(mx);
    float sum = 0.f;
    for (int c = 0; c < cnt; c++) { v[c] = __expf(v[c] - mx); sum += v[c]; }
    sum = blkredSum(sum);
    float inv = 1.0f / sum;
    for (int c = 0; c < cnt; c++) S[c * 256 + tid] = v[c] * inv;
}

// ---------- accumulate c_part[s][b,h,:] = sum_j p*x — bf16 X, vector p-pairs ----------
// grid (2, BB, 16), block 128
__global__ void accum_k(const __nv_bfloat16* __restrict__ X, int Nkv) {
    int b = blockIdx.y, s = blockIdx.z, tid = threadIdx.x;
    int d0 = blockIdx.x * 512 + tid * 4;
    int Nt = Nkv >> 4;
    int jbase = s * Nt;
    __shared__ unsigned long long ps[16][64];  // {p,p}
    unsigned long long acc01[16], acc23[16];
#pragma unroll
    for (int h = 0; h < 16; h++) { acc01[h] = 0ull; acc23[h] = 0ull; }
    for (int jc = 0; jc < Nt; jc += 64) {
        for (int t = tid; t < 1024; t += 128) {
            int h = t >> 6, jj = t & 63;
            float p = g_scores[((size_t)b * HH + h) * Nkv + jbase + jc + jj];
            ps[h][jj] = pack2(p, p);
        }
        __syncthreads();
        const __nv_bfloat16* Xb = X + ((size_t)b * Nkv + jbase + jc) * DD + d0;
        for (int j4 = 0; j4 < 64; j4 += 4) {
            uint2 v0 = *(const uint2*)(Xb + (size_t)(j4 + 0) * DD);
            uint2 v1 = *(const uint2*)(Xb + (size_t)(j4 + 1) * DD);
            uint2 v2 = *(const uint2*)(Xb + (size_t)(j4 + 2) * DD);
            uint2 v3 = *(const uint2*)(Xb + (size_t)(j4 + 3) * DD);
            unsigned long long x01[4], x23[4];
            x01[0] = bfpair(v0.x); x23[0] = bfpair(v0.y);
            x01[1] = bfpair(v1.x); x23[1] = bfpair(v1.y);
            x01[2] = bfpair(v2.x); x23[2] = bfpair(v2.y);
            x01[3] = bfpair(v3.x); x23[3] = bfpair(v3.y);
#pragma unroll
            for (int h = 0; h < 16; h++) {
                ulonglong2 p01 = *(const ulonglong2*)&ps[h][j4];
                ulonglong2 p23 = *(const ulonglong2*)&ps[h][j4 + 2];
                ffma2(acc01[h], x01[0], p01.x); ffma2(acc23[h], x23[0], p01.x);
                ffma2(acc01[h], x01[1], p01.y); ffma2(acc23[h], x23[1], p01.y);
                ffma2(acc01[h], x01[2], p23.x); ffma2(acc23[h], x23[2], p23.x);
                ffma2(acc01[h], x01[3], p23.y); ffma2(acc23[h], x23[3], p23.y);
            }
        }
        __syncthreads();
    }
#pragma unroll
    for (int h = 0; h < 16; h++) {
        float2 a = unpack2(acc01[h]);
        float2 c = unpack2(acc23[h]);
        *(float4*)(g_cpart + ((size_t)(s * BB + b) * HH + h) * DD + d0) =
            make_float4(a.x, a.y, c.x, c.y);
    }
}

// ---------- host side ----------
struct Scratch {
    float *q, *x, *qkv, *attn, *qp, *c, *part, *cpart, *h;
    __nv_bfloat16 *ftb, *kvb;
};

static void cross_attn(const Scratch& S, const __nv_bfloat16* X, int Nkv,
                       const float* inW, const float* inB,
                       const float* outW, const float* outB, int tok) {
    gemm_k<<<dim3(16, 1, 8), 256>>>(S.x + tok * DD, 2 * DD, 0, inW, DD, 0, S.part, DD, BB, DD, 8);
    combine_k<<<128, 256>>>(S.part, 8, BB, DD, nullptr, 0, S.qp, DD, 0, 0, BB * DD);
    u_k<<<dim3(HH, DD / 64), 256>>>(inW + (size_t)DD * DD, inB);
    score_k<<<dim3(Nkv / 128, BB), 128>>>(X, Nkv);
    softmax_k<<<BB * HH, 256>>>(Nkv);
    accum_k<<<dim3(2, BB, 16), 128>>>(X, Nkv);
    combine_k<<<2048, 256>>>(S.cpart, 16, BB * HH, DD, nullptr, 0, S.c, DD, 0, 0, BB * HH * DD);
    gemm_k<<<dim3(1, 1, HH * 8), 256>>>(S.c, HH * DD, DD, inW + (size_t)2 * DD * DD, DD,
                                        (long long)64 * DD, S.part, 64, BB, DD, 8);
    combine_k<<<128, 256>>>(S.part, 8, BB, 64, inB + 2 * DD, 64, S.qp, DD, 64, 0, HH * BB * 64);
    gemm_k<<<dim3(16, 1, 8), 256>>>(S.qp, DD, 0, outW, DD, 0, S.part, DD, BB, DD, 8);
    combine_k<<<128, 256>>>(S.part, 8, BB, DD, outB, 0, S.q + tok * DD, 2 * DD, 0, 2, BB * DD);
}

extern "C" void kernel_launch(void* const* d_in, const int* in_sizes, int n_in,
                              void* d_out, int out_size) {
    const float* FT   = (const float*)d_in[0];
    const float* KV   = (const float*)d_in[1];
    const float* MAXI = (const float*)d_in[2];
    const float* QB   = (const float*)d_in[3];
    const float* RW   = (const float*)d_in[4];
    const float* TW   = (const float*)d_in[5];
    const float* LN1G = (const float*)d_in[6];
    const float* LN1B = (const float*)d_in[7];
    const float* SAIW = (const float*)d_in[8];
    const float* SAIB = (const float*)d_in[9];
    const float* SAOW = (const float*)d_in[10];
    const float* SAOB = (const float*)d_in[11];
    const float* LN2G = (const float*)d_in[12];
    const float* LN2B = (const float*)d_in[13];
    const float* CGIW = (const float*)d_in[14];
    const float* CGIB = (const float*)d_in[15];
    const float* CGOW = (const float*)d_in[16];
    const float* CGOB = (const float*)d_in[17];
    const float* CSIW = (const float*)d_in[18];
    const float* CSIB = (const float*)d_in[19];
    const float* CSOW = (const float*)d_in[20];
    const float* CSOB = (const float*)d_in[21];
    const float* LN3G = (const float*)d_in[22];
    const float* LN3B = (const float*)d_in[23];
    const float* F1W  = (const float*)d_in[24];
    const float* F1B  = (const float*)d_in[25];
    const float* F2W  = (const float*)d_in[26];
    const float* F2B  = (const float*)d_in[27];
    const float* OUTG = (const float*)d_in[28];
    const float* OUTB = (const float*)d_in[29];
    const int*   FIDX = (const int*)d_in[30];

    Scratch S;
    cudaGetSymbolAddress((void**)&S.q,     g_q);
    cudaGetSymbolAddress((void**)&S.x,     g_x);
    cudaGetSymbolAddress((void**)&S.qkv,   g_qkv);
    cudaGetSymbolAddress((void**)&S.attn,  g_attn);
    cudaGetSymbolAddress((void**)&S.qp,    g_qp);
    cudaGetSymbolAddress((void**)&S.c,     g_c);
    cudaGetSymbolAddress((void**)&S.part,  g_part);
    cudaGetSymbolAddress((void**)&S.cpart, g_cpart);
    cudaGetSymbolAddress((void**)&S.h,     g_h);
    cudaGetSymbolAddress((void**)&S.ftb,   g_ftb);
    cudaGetSymbolAddress((void**)&S.kvb,   g_kvb);

    meanpart_k<<<dim3(2, BB, MS), 128>>>(FT);
    conv_k<<<(BB * KVN * DD) / 1024, 256>>>(KV, S.kvb);
    initq_k<<<256, 256>>>(MAXI, QB, RW, TW, FIDX);

    for (int l = 0; l < LL; l++) {
        size_t o1 = (size_t)l * DD, o3 = (size_t)l * 3 * DD;
        size_t oDD = (size_t)l * DD * DD, o3DD = (size_t)l * 3 * DD * DD;
        size_t o4DD = (size_t)l * 4 * DD * DD, o4D = (size_t)l * 4 * DD;
        // self-attn
        ln_k<<<64, 256>>>(S.q, LN1G + o1, LN1B + o1, S.x);
        gemm_k<<<dim3(48, 1, 8), 256>>>(S.x, DD, 0, SAIW + o3DD, DD, 0, S.part, 3 * DD, 64, DD, 8);
        combine_k<<<768, 256>>>(S.part, 8, 64, 3 * DD, SAIB + o3, 0, S.qkv, 3 * DD, 0, 0, 64 * 3 * DD);
        sattn_k<<<dim3(BB, HH), 64>>>();
        gemm_k<<<dim3(16, 1, 8), 256>>>(S.attn, DD, 0, SAOW + oDD, DD, 0, S.part, DD, 64, DD, 8);
        combine_k<<<256, 256>>>(S.part, 8, 64, DD, SAOB + o1, 0, S.q, DD, 0, 2, 64 * DD);
        // cross-attn (token 0 over frame_tokens, token 1 over kv_salient)
        ln_k<<<64, 256>>>(S.q, LN2G + o1, LN2B + o1, S.x);
        cross_attn(S, S.ftb, NN, CGIW + o3DD, CGIB + o3, CGOW + oDD, CGOB + o1, 0);
        cross_attn(S, S.kvb, KVN, CSIW + o3DD, CSIB + o3, CSOW + oDD, CSOB + o1, 1);
        // FFN
        ln_k<<<64, 256>>>(S.q, LN3G + o1, LN3B + o1, S.x);
        gemm_k<<<dim3(64, 1, 8), 256>>>(S.x, DD, 0, F1W + o4DD, DD, 0, S.part, 4 * DD, 64, DD, 8);
        combine_k<<<1024, 256>>>(S.part, 8, 64, 4 * DD, F1B + o4D, 0, S.h, 4 * DD, 0, 1, 64 * 4 * DD);
        gemm_k<<<dim3(16, 1, 16), 256>>>(S.h, 4 * DD, 0, F2W + o4DD, 4 * DD, 0, S.part, DD, 64, 4 * DD, 16);
        combine_k<<<256, 256>>>(S.part, 16, 64, DD, F2B + o1, 0, S.q, DD, 0, 2, 64 * DD);
    }
    ln_k<<<64, 256>>>(S.q, OUTG, OUTB, (float*)d_out);
}